// round 11
// baseline (speedup 1.0000x reference)
#include <cuda_runtime.h>
#include <cuda_fp16.h>
#include <cstdint>

// ConvTranspose2d (k==s==2) == GEMM: M=32768 pixels, N=1024 (o*4+i*2+j), K=512 (c)
// Single-pass fp16 mma (fp32 accumulate): rel_err ~2.8e-4 < 1e-3 gate (measured).
// NEW: NO x prepass. GEMM stages A as fp32 straight from x ([c][p] layout) via
// cp.async (2-stage), converts fp32->fp16 in-smem each iteration (hidden under the
// saturated HMMA pipe), and consumes A with ldmatrix.x4.trans (R9-proven).
// B: tiny w transpose prepass -> g_wF [1024][512] fp16, 2-stage cp.async.
// 256 thr / 8 warps (4Mx2N), warp tile 32x64, 2 CTAs/SM, BK=64.

#define M_TOTAL 32768
#define K_TOTAL 512
#define N_TOTAL 1024
#define BM 128
#define BN 128
#define BK 64
#define KITERS (K_TOTAL / BK)

#define A32ROWB 512                    // A32 row: 128 p fp32
#define A16ROWB 256                    // A16 row: 128 p fp16
#define BROWB   128                    // B row: 64 k fp16

#define A32_STAGE (64 * A32ROWB)       // 32KB
#define B_STAGE   (128 * BROWB)        // 16KB
#define OFF_A32 0                      // 2 stages: 64KB
#define OFF_A16 (2 * A32_STAGE)        // 1 buffer: 16KB
#define OFF_B   (OFF_A16 + 64 * A16ROWB)   // 2 stages: 32KB
#define SMEM_TOTAL (OFF_B + 2 * B_STAGE)   // 112KB -> 2 CTAs/SM (224KB <= 228KB)

// -------- device scratch (allocation-free rule: __device__ globals) --------
__device__ __half g_wF[(size_t)N_TOTAL * K_TOTAL];   // [n][k]

// ---------------- helpers ----------------
__device__ __forceinline__ uint32_t smem_u32(const void* p) {
    uint32_t a;
    asm("{ .reg .u64 t; cvta.to.shared.u64 t, %1; cvt.u32.u64 %0, t; }" : "=r"(a) : "l"(p));
    return a;
}

#define CP_ASYNC16(dst, src) \
    asm volatile("cp.async.cg.shared.global [%0], [%1], 16;" :: "r"(dst), "l"(src) : "memory")
#define CP_COMMIT()  asm volatile("cp.async.commit_group;" ::: "memory")
#define CP_WAIT0()   asm volatile("cp.async.wait_group 0;" ::: "memory")

#define LDMX4(R, addr)                                                          \
    asm volatile("ldmatrix.sync.aligned.m8n8.x4.shared.b16 {%0,%1,%2,%3}, [%4];"\
        : "=r"((R)[0]), "=r"((R)[1]), "=r"((R)[2]), "=r"((R)[3]) : "r"(addr))
#define LDMX4T(R, addr)                                                         \
    asm volatile("ldmatrix.sync.aligned.m8n8.x4.trans.shared.b16 {%0,%1,%2,%3}, [%4];"\
        : "=r"((R)[0]), "=r"((R)[1]), "=r"((R)[2]), "=r"((R)[3]) : "r"(addr))

#define MMA16816(ACC, A, B)                                                     \
    asm volatile("mma.sync.aligned.m16n8k16.row.col.f32.f16.f16.f32 "           \
        "{%0,%1,%2,%3}, {%4,%5,%6,%7}, {%8,%9}, {%0,%1,%2,%3};"                 \
        : "+f"((ACC)[0]), "+f"((ACC)[1]), "+f"((ACC)[2]), "+f"((ACC)[3])        \
        : "r"((A)[0]), "r"((A)[1]), "r"((A)[2]), "r"((A)[3]),                   \
          "r"((B)[0]), "r"((B)[1]))

// ---------------- Phase 1: w transpose + fp16 convert (tiny) ----------------
// src: [R][C] fp32 -> dst: [C][R] fp16
__global__ void tsplit_kernel(const float* __restrict__ src,
                              __half* __restrict__ dst,
                              int R, int C)
{
    __shared__ float tile[64][33];
    int p0 = blockIdx.x * 32;
    int c0 = blockIdx.y * 64;
    int tx = threadIdx.x, ty = threadIdx.y;
    #pragma unroll
    for (int i = 0; i < 64; i += 8)
        tile[ty + i][tx] = src[(size_t)(c0 + ty + i) * C + p0 + tx];
    __syncthreads();
    #pragma unroll
    for (int j = 0; j < 32; j += 8) {
        int p = ty + j;
        __half2 v = __floats2half2_rn(tile[tx * 2][p], tile[tx * 2 + 1][p]);
        *(__half2*)(dst + (size_t)(p0 + p) * R + c0 + tx * 2) = v;
    }
}

// ---------------- Phase 2: fused convert + mma.sync fp16 GEMM ----------------
// A32 stage: 64 c-rows x 512B; fp32 chunk c32 (0..31) at ((c32 ^ (r&7))<<4).
// A16:       64 c-rows x 256B; fp16 chunk cm (0..15) at ((cm ^ (r&7))<<4)
//            (exact R9 trans-ldmatrix layout).
// B stage:   128 n-rows x 128B; chunk c (0..7) at ((c ^ (r&7))<<4).

__global__ __launch_bounds__(256, 2)
void gemm_mma_kernel(const float* __restrict__ x,
                     const float* __restrict__ bias, float* __restrict__ out)
{
    extern __shared__ char smem[];
    const uint32_t sbase = smem_u32(smem);

    const int tid  = threadIdx.x;
    const int lane = tid & 31;
    const int warp = tid >> 5;
    const int g    = lane >> 2;       // mma row within fragment
    const int tg   = lane & 3;        // mma col-pair selector
    const int wm   = warp & 3;        // 4 warps along M (32 rows each)
    const int wn   = warp >> 2;       // 2 warps along N (64 cols each)

    const int nb = blockIdx.x;        // 0..7   (N tile of 128)
    const int mb = blockIdx.y;        // 0..255 (M tile of 128)

    const int batch = mb >> 5;                       // 32 M-tiles per batch plane
    const int pin   = (mb & 31) * BM;                // pixel offset in plane
    const float*  gA = x + (size_t)batch * K_TOTAL * 4096;   // fp32 [c][p] plane
    const __half* gB = g_wF + (size_t)nb * BN * K_TOTAL;

    // ---- A trans-ldmatrix lane addressing (fragment [m16][k16] from [k][m]) ----
    const int krL = (lane & 7) + ((lane >> 4) << 3);    // k-row within 16
    const int cmL = (lane >> 3) & 1;                    // m-chunk (8p=16B) within 16
    // ---- B ldmatrix addressing ----
    const int x7   = lane & 7;
    const int rB   = ((lane >> 4) << 3) + x7;           // row-in-16, B x4 (nt pair)
    const int selB = (lane >> 3) & 1;                   // k8 select, B x4
    const uint32_t bBase = (uint32_t)(wn * 64 + rB) * BROWB;

    float acc[2][8][4];
    #pragma unroll
    for (int i = 0; i < 2; i++)
        #pragma unroll
        for (int j = 0; j < 8; j++)
            #pragma unroll
            for (int r = 0; r < 4; r++) acc[i][j][r] = 0.f;

    // ---- async staging of one k-stage (BK=64) ----
    auto stage_load = [&](int it, int buf) {
        const int k0 = it * BK;
        const uint32_t sA = sbase + OFF_A32 + buf * A32_STAGE;
        const uint32_t sB = sbase + OFF_B + buf * B_STAGE;
        #pragma unroll
        for (int i = 0; i < 8; i++) {                 // A32: 2048 x 16B chunks
            int q = tid + i * 256;
            int r = q >> 5, c32 = q & 31;
            CP_ASYNC16(sA + (uint32_t)r * A32ROWB + (uint32_t)((c32 ^ (r & 7)) << 4),
                       gA + (size_t)(k0 + r) * 4096 + pin + c32 * 4);
        }
        #pragma unroll
        for (int i = 0; i < 4; i++) {                 // B: 1024 x 16B chunks
            int q = tid + i * 256;
            int r = q >> 3, c = q & 7;
            CP_ASYNC16(sB + (uint32_t)r * BROWB + (uint32_t)((c ^ (r & 7)) << 4),
                       gB + (size_t)r * K_TOTAL + k0 + c * 8);
        }
    };

    // prologue
    stage_load(0, 0);
    CP_COMMIT();

    for (int it = 0; it < KITERS; it++) {
        CP_WAIT0();               // stage `it` arrived (only outstanding group)
        __syncthreads();          // sync1: data visible; prev iter's mma/convert done

        if (it + 1 < KITERS) {    // prefetch next stage (~1 full iter of cover)
            stage_load(it + 1, (it + 1) & 1);
            CP_COMMIT();
        }

        // ---- convert A32[it&1] -> A16 (layout-preserving, fp32->fp16) ----
        {
            const char* a32 = smem + OFF_A32 + (it & 1) * A32_STAGE;
            char* a16 = smem + OFF_A16;
            #pragma unroll
            for (int i = 0; i < 4; i++) {             // 1024 A16 chunks of 16B
                int q = tid + i * 256;
                int kr = q >> 4, cm = q & 15;
                int sw = kr & 7;
                const float4 u = *(const float4*)(a32 + kr * A32ROWB
                                                  + (((2 * cm)     ^ sw) << 4));
                const float4 v = *(const float4*)(a32 + kr * A32ROWB
                                                  + (((2 * cm + 1) ^ sw) << 4));
                __half2 h0 = __floats2half2_rn(u.x, u.y);
                __half2 h1 = __floats2half2_rn(u.z, u.w);
                __half2 h2 = __floats2half2_rn(v.x, v.y);
                __half2 h3 = __floats2half2_rn(v.z, v.w);
                uint4 st;
                st.x = *(uint32_t*)&h0; st.y = *(uint32_t*)&h1;
                st.z = *(uint32_t*)&h2; st.w = *(uint32_t*)&h3;
                *(uint4*)(a16 + kr * A16ROWB + ((cm ^ sw) << 4)) = st;
            }
        }
        __syncthreads();          // sync2: A16 ready for ldmatrix

        const uint32_t sA16 = sbase + OFF_A16;
        const uint32_t sB   = sbase + OFF_B + (it & 1) * B_STAGE;

        #pragma unroll
        for (int kc = 0; kc < 4; kc++) {              // four k16 chunks in BK=64
            uint32_t a[8], b[16];
            #pragma unroll
            for (int mt = 0; mt < 2; mt++) {
                int kr = kc * 16 + krL;
                int cm = wm * 4 + mt * 2 + cmL;
                LDMX4T(a + mt * 4,
                       sA16 + (uint32_t)kr * A16ROWB + (uint32_t)((cm ^ (kr & 7)) << 4));
            }
            #pragma unroll
            for (int ntp = 0; ntp < 4; ntp++)         // each LDMX4 covers 2 nt
                LDMX4(b + ntp * 4, sB + bBase + (uint32_t)ntp * 16 * BROWB
                                   + (uint32_t)(((kc * 2 + selB) ^ x7) << 4));
            #pragma unroll
            for (int mt = 0; mt < 2; mt++)
                #pragma unroll
                for (int nt = 0; nt < 8; nt++)
                    MMA16816(acc[mt][nt], a + mt * 4, b + nt * 2);
        }
    }

    // ---- epilogue: scatter to out[b][o][2h+i][2w+j], fused bias, streaming ----
    #pragma unroll
    for (int mt = 0; mt < 2; mt++) {
        int r0 = mb * 128 + wm * 32 + mt * 16 + g;
        #pragma unroll
        for (int half = 0; half < 2; half++) {
            int p  = r0 + half * 8;
            int bb = p >> 12;
            int h  = (p >> 6) & 63;
            int wp = p & 63;
            #pragma unroll
            for (int nt = 0; nt < 8; nt++) {
                int n  = nb * 128 + wn * 64 + nt * 8 + tg * 2;   // even -> (j=0, j=1)
                int o  = n >> 2;
                int ii = (n >> 1) & 1;
                float bo = __ldg(bias + o);
                size_t addr = (((size_t)(bb * 256 + o) * 128) + (h * 2 + ii)) * 128 + wp * 2;
                float2 v;
                v.x = acc[mt][nt][half * 2 + 0] + bo;
                v.y = acc[mt][nt][half * 2 + 1] + bo;
                __stcs((float2*)(out + addr), v);
            }
        }
    }
}

// ---------------- launch (single stream) ----------------
extern "C" void kernel_launch(void* const* d_in, const int* in_sizes, int n_in,
                              void* d_out, int out_size)
{
    const float* x    = (const float*)d_in[0];   // [8,512,64,64]
    const float* wgt  = (const float*)d_in[1];   // [512,256,2,2] -> [512][1024]
    const float* bias = (const float*)d_in[2];   // [256]
    float* out = (float*)d_out;                  // [8,256,128,128]

    void* pwF;
    cudaGetSymbolAddress(&pwF, g_wF);

    // Phase 1: w transpose [512][1024] -> [1024][512] fp16 (tiny)
    tsplit_kernel<<<dim3(1024 / 32, 512 / 64, 1), dim3(32, 8)>>>(
        wgt, (__half*)pwF, 512, 1024);

    // Phase 2: fused convert+GEMM
    static int attr_set = 0;
    if (!attr_set) {
        cudaFuncSetAttribute(gemm_mma_kernel,
                             cudaFuncAttributeMaxDynamicSharedMemorySize, SMEM_TOTAL);
        attr_set = 1;
    }
    dim3 grid(N_TOTAL / BN, M_TOTAL / BM);   // (8, 256) — nb fastest for A-slab L2 reuse
    gemm_mma_kernel<<<grid, 256, SMEM_TOTAL>>>(x, bias, out);
}

// round 12
// speedup vs baseline: 1.0677x; 1.0677x over previous
#include <cuda_runtime.h>
#include <cuda_fp16.h>
#include <cstdint>

// ConvTranspose2d (k==s==2) == GEMM: M=32768 pixels, N=1024 (o*4+i*2+j), K=512 (c)
// Single-pass fp16 mma (fp32 accumulate): rel_err ~2.8e-4 < 1e-3 gate (measured).
// Phase 1: transpose+convert  x -> g_xF [32768][512] fp16,  w -> g_wF [1024][512]
//          (64x64 tiles, float4 global loads, uint4 fp16 stores: full 128B
//           transactions both directions).
// Phase 2: mma.sync fp16 GEMM — R8-best mainloop verbatim (256 thr / 8 warps
//          (4Mx2N), warp tile 32x64, 2 CTAs/SM, BK=64, 3-stage cp.async,
//          1 sync/iter) + __stcs streaming epilogue stores.

#define M_TOTAL 32768
#define K_TOTAL 512
#define N_TOTAL 1024
#define BM 128
#define BN 128
#define BK 64
#define KITERS (K_TOTAL / BK)
#define ROWB 128                       // bytes per smem row (64 fp16)
#define STAGE_BYTES (2 * 128 * ROWB)   // A 16KB + B 16KB
#define NSTAGE 3
#define SMEM_TOTAL (NSTAGE * STAGE_BYTES)   // 96KB -> 2 CTAs/SM

// -------- device scratch (allocation-free rule: __device__ globals) --------
__device__ __half g_xF[(size_t)M_TOTAL * K_TOTAL];   // [p][c]
__device__ __half g_wF[(size_t)N_TOTAL * K_TOTAL];   // [n][k]

// ---------------- helpers ----------------
__device__ __forceinline__ uint32_t smem_u32(const void* p) {
    uint32_t a;
    asm("{ .reg .u64 t; cvta.to.shared.u64 t, %1; cvt.u32.u64 %0, t; }" : "=r"(a) : "l"(p));
    return a;
}

#define CP_ASYNC16(dst, src) \
    asm volatile("cp.async.cg.shared.global [%0], [%1], 16;" :: "r"(dst), "l"(src) : "memory")
#define CP_COMMIT()  asm volatile("cp.async.commit_group;" ::: "memory")
#define CP_WAIT1()   asm volatile("cp.async.wait_group 1;" ::: "memory")
#define CP_WAIT0()   asm volatile("cp.async.wait_group 0;" ::: "memory")

#define LDMX4(R, addr)                                                          \
    asm volatile("ldmatrix.sync.aligned.m8n8.x4.shared.b16 {%0,%1,%2,%3}, [%4];"\
        : "=r"((R)[0]), "=r"((R)[1]), "=r"((R)[2]), "=r"((R)[3]) : "r"(addr))

#define MMA16816(ACC, A, B)                                                     \
    asm volatile("mma.sync.aligned.m16n8k16.row.col.f32.f16.f16.f32 "           \
        "{%0,%1,%2,%3}, {%4,%5,%6,%7}, {%8,%9}, {%0,%1,%2,%3};"                 \
        : "+f"((ACC)[0]), "+f"((ACC)[1]), "+f"((ACC)[2]), "+f"((ACC)[3])        \
        : "r"((A)[0]), "r"((A)[1]), "r"((A)[2]), "r"((A)[3]),                   \
          "r"((B)[0]), "r"((B)[1]))

// ---------------- Phase 1: transpose + fp16 convert (wide) ----------------
// src: [R][C] fp32 -> dst: [C][R] fp16.  64x64 tile, 256 threads.
// Load: 1024 float4 (4/thread), coalesced 128B lines.
// Store: 512 uint4 (2/thread); each 8-lane group writes one full 128B dst row.
__global__ __launch_bounds__(256)
void tsplit_kernel(const float* __restrict__ src,
                   __half* __restrict__ dst,
                   int R, int C)
{
    __shared__ float tile[64][65];
    int p0 = blockIdx.x * 64;
    int c0 = blockIdx.y * 64;
    int tid = threadIdx.x;

    #pragma unroll
    for (int i = 0; i < 4; i++) {            // 1024 float4 chunks
        int q = tid + i * 256;
        int r = q >> 4;                      // c-row 0..63
        int c4 = q & 15;                     // float4 col 0..15
        float4 v = *(const float4*)(src + (size_t)(c0 + r) * C + p0 + c4 * 4);
        tile[r][c4 * 4 + 0] = v.x;
        tile[r][c4 * 4 + 1] = v.y;
        tile[r][c4 * 4 + 2] = v.z;
        tile[r][c4 * 4 + 3] = v.w;
    }
    __syncthreads();

    #pragma unroll
    for (int i = 0; i < 2; i++) {            // 512 uint4 chunks
        int q = tid + i * 256;
        int pr = q >> 3;                     // p-row 0..63
        int c8 = q & 7;                      // 8-channel group 0..7
        __half2 h[4];
        #pragma unroll
        for (int j = 0; j < 4; j++)
            h[j] = __floats2half2_rn(tile[c8 * 8 + j * 2][pr],
                                     tile[c8 * 8 + j * 2 + 1][pr]);
        uint4 st;
        st.x = *(uint32_t*)&h[0];
        st.y = *(uint32_t*)&h[1];
        st.z = *(uint32_t*)&h[2];
        st.w = *(uint32_t*)&h[3];
        *(uint4*)(dst + (size_t)(p0 + pr) * R + c0 + c8 * 8) = st;
    }
}

// ---------------- Phase 2: mma.sync fp16 GEMM (R8-best mainloop) ----------------
// SMEM stage: A = 128 rows x 128B, B = 128 rows x 128B.
// Row r, 16B chunk c stored at ((c ^ (r&7))<<4): conflict-free for cp.async
// stores and all ldmatrix phases.

__global__ __launch_bounds__(256, 2)
void gemm_mma_kernel(const float* __restrict__ bias, float* __restrict__ out)
{
    extern __shared__ char smem[];
    const uint32_t sbase = smem_u32(smem);

    const int tid  = threadIdx.x;
    const int lane = tid & 31;
    const int warp = tid >> 5;
    const int g    = lane >> 2;       // mma row within fragment
    const int tg   = lane & 3;        // mma col-pair selector
    const int wm   = warp & 3;        // 4 warps along M (32 rows each)
    const int wn   = warp >> 2;       // 2 warps along N (64 cols each)

    const int nb = blockIdx.x;        // 0..7   (N tile of 128)
    const int mb = blockIdx.y;        // 0..255 (M tile of 128)

    const __half* gA = g_xF + (size_t)mb * BM * K_TOTAL;
    const __half* gB = g_wF + (size_t)nb * BN * K_TOTAL;

    // ldmatrix per-lane addressing
    const int x7   = lane & 7;
    const int rA   = x7 + ((lane >> 3) & 1) * 8;          // row-in-16, A x4
    const int selA = lane >> 4;                           // k8 select, A x4
    const int rB   = ((lane >> 4) << 3) + x7;             // row-in-16, B x4 (nt pair)
    const int selB = (lane >> 3) & 1;                     // k8 select, B x4
    const uint32_t aBase = (uint32_t)(wm * 32 + rA) * ROWB;
    const uint32_t bBase = (uint32_t)(wn * 64 + rB) * ROWB;

    float acc[2][8][4];
    #pragma unroll
    for (int i = 0; i < 2; i++)
        #pragma unroll
        for (int j = 0; j < 8; j++)
            #pragma unroll
            for (int r = 0; r < 4; r++) acc[i][j][r] = 0.f;

    // ---- async staging of one k-stage (BK=64) into stage buffer ----
    auto stage_load = [&](int it, int buf) {
        const int k0 = it * BK;
        const uint32_t sA = sbase + buf * STAGE_BYTES;
        const uint32_t sB = sA + 128 * ROWB;
        #pragma unroll
        for (int i = 0; i < 4; i++) {                 // A: 1024 x 16B chunks
            int q = tid + i * 256;
            int r = q >> 3, c = q & 7;
            CP_ASYNC16(sA + (uint32_t)r * ROWB + (uint32_t)((c ^ (r & 7)) << 4),
                       gA + (size_t)r * K_TOTAL + k0 + c * 8);
        }
        #pragma unroll
        for (int i = 0; i < 4; i++) {                 // B: 1024 x 16B chunks
            int q = tid + i * 256;
            int r = q >> 3, c = q & 7;
            CP_ASYNC16(sB + (uint32_t)r * ROWB + (uint32_t)((c ^ (r & 7)) << 4),
                       gB + (size_t)r * K_TOTAL + k0 + c * 8);
        }
    };

    // prologue: two stages in flight
    stage_load(0, 0);
    CP_COMMIT();
    stage_load(1, 1);
    CP_COMMIT();

    for (int it = 0; it < KITERS; it++) {
        if (it + 1 < KITERS) { CP_WAIT1(); } else { CP_WAIT0(); }
        __syncthreads();          // releases compute(it) + certifies (it+2)%3 buffer
        if (it + 2 < KITERS) {
            stage_load(it + 2, (it + 2) % NSTAGE);
            CP_COMMIT();
        }

        const uint32_t sA = sbase + (it % NSTAGE) * STAGE_BYTES;
        const uint32_t sB = sA + 128 * ROWB;

        #pragma unroll
        for (int kc = 0; kc < 4; kc++) {              // four k16 chunks in BK=64
            uint32_t a[8], b[16];
            #pragma unroll
            for (int mt = 0; mt < 2; mt++)
                LDMX4(a + mt * 4, sA + aBase + (uint32_t)mt * 16 * ROWB
                                  + (uint32_t)(((kc * 2 + selA) ^ x7) << 4));
            #pragma unroll
            for (int ntp = 0; ntp < 4; ntp++)         // each LDMX4 covers 2 nt
                LDMX4(b + ntp * 4, sB + bBase + (uint32_t)ntp * 16 * ROWB
                                   + (uint32_t)(((kc * 2 + selB) ^ x7) << 4));
            #pragma unroll
            for (int mt = 0; mt < 2; mt++)
                #pragma unroll
                for (int nt = 0; nt < 8; nt++)
                    MMA16816(acc[mt][nt], a + mt * 4, b + nt * 2);
        }
    }

    // ---- epilogue: scatter to out[b][o][2h+i][2w+j], fused bias, streaming ----
    #pragma unroll
    for (int mt = 0; mt < 2; mt++) {
        int r0 = mb * 128 + wm * 32 + mt * 16 + g;
        #pragma unroll
        for (int half = 0; half < 2; half++) {
            int p  = r0 + half * 8;
            int bb = p >> 12;
            int h  = (p >> 6) & 63;
            int wp = p & 63;
            #pragma unroll
            for (int nt = 0; nt < 8; nt++) {
                int n  = nb * 128 + wn * 64 + nt * 8 + tg * 2;   // even -> (j=0, j=1)
                int o  = n >> 2;
                int ii = (n >> 1) & 1;
                float bo = __ldg(bias + o);
                size_t addr = (((size_t)(bb * 256 + o) * 128) + (h * 2 + ii)) * 128 + wp * 2;
                float2 v;
                v.x = acc[mt][nt][half * 2 + 0] + bo;
                v.y = acc[mt][nt][half * 2 + 1] + bo;
                __stcs((float2*)(out + addr), v);
            }
        }
    }
}

// ---------------- launch ----------------
extern "C" void kernel_launch(void* const* d_in, const int* in_sizes, int n_in,
                              void* d_out, int out_size)
{
    const float* x    = (const float*)d_in[0];   // [8,512,64,64]
    const float* wgt  = (const float*)d_in[1];   // [512,256,2,2] -> [512][1024]
    const float* bias = (const float*)d_in[2];   // [256]
    float* out = (float*)d_out;                  // [8,256,128,128]

    void *pxF, *pwF;
    cudaGetSymbolAddress(&pxF, g_xF);
    cudaGetSymbolAddress(&pwF, g_wF);
    __half* xF = (__half*)pxF;
    __half* wF = (__half*)pwF;

    // Phase 1: per-batch x transpose [512][4096] -> [4096][512]; w -> [1024][512]
    for (int b = 0; b < 8; b++)
        tsplit_kernel<<<dim3(4096 / 64, 512 / 64), 256>>>(
            x  + (size_t)b * K_TOTAL * 4096,
            xF + (size_t)b * 4096 * K_TOTAL, 512, 4096);
    tsplit_kernel<<<dim3(1024 / 64, 512 / 64), 256>>>(wgt, wF, 512, 1024);

    // Phase 2
    static int attr_set = 0;
    if (!attr_set) {
        cudaFuncSetAttribute(gemm_mma_kernel,
                             cudaFuncAttributeMaxDynamicSharedMemorySize, SMEM_TOTAL);
        attr_set = 1;
    }
    dim3 grid(N_TOTAL / BN, M_TOTAL / BM);   // (8, 256) — nb fastest for A-tile L2 reuse
    gemm_mma_kernel<<<grid, 256, SMEM_TOTAL>>>(bias, out);
}

// round 13
// speedup vs baseline: 1.2430x; 1.1642x over previous
#include <cuda_runtime.h>
#include <cuda_fp16.h>
#include <cstdint>

// ConvTranspose2d (k==s==2) == GEMM: M=32768 pixels, N=1024 (o*4+i*2+j), K=512 (c)
// Single-pass fp16 mma (fp32 accumulate): rel_err ~2.8e-4 < 1e-3 gate (measured).
// Phase 1: transpose+convert in ONE launch (blockIdx.z = batch):
//          x -> g_xF [32768][512] fp16, 64x64 tiles, float4 loads, uint4 stores.
//          w -> g_wF [1024][512] fp16 (tiny second launch).
// Phase 2: mma.sync fp16 GEMM — R8-best mainloop (256 thr / 8 warps (4Mx2N),
//          warp tile 32x64, 2 CTAs/SM, BK=64, 3-stage cp.async, 1 sync/iter)
//          + __stcs streaming epilogue stores.

#define M_TOTAL 32768
#define K_TOTAL 512
#define N_TOTAL 1024
#define BM 128
#define BN 128
#define BK 64
#define KITERS (K_TOTAL / BK)
#define ROWB 128                       // bytes per smem row (64 fp16)
#define STAGE_BYTES (2 * 128 * ROWB)   // A 16KB + B 16KB
#define NSTAGE 3
#define SMEM_TOTAL (NSTAGE * STAGE_BYTES)   // 96KB -> 2 CTAs/SM

// -------- device scratch (allocation-free rule: __device__ globals) --------
__device__ __half g_xF[(size_t)M_TOTAL * K_TOTAL];   // [p][c]
__device__ __half g_wF[(size_t)N_TOTAL * K_TOTAL];   // [n][k]

// ---------------- helpers ----------------
__device__ __forceinline__ uint32_t smem_u32(const void* p) {
    uint32_t a;
    asm("{ .reg .u64 t; cvta.to.shared.u64 t, %1; cvt.u32.u64 %0, t; }" : "=r"(a) : "l"(p));
    return a;
}

#define CP_ASYNC16(dst, src) \
    asm volatile("cp.async.cg.shared.global [%0], [%1], 16;" :: "r"(dst), "l"(src) : "memory")
#define CP_COMMIT()  asm volatile("cp.async.commit_group;" ::: "memory")
#define CP_WAIT1()   asm volatile("cp.async.wait_group 1;" ::: "memory")
#define CP_WAIT0()   asm volatile("cp.async.wait_group 0;" ::: "memory")

#define LDMX4(R, addr)                                                          \
    asm volatile("ldmatrix.sync.aligned.m8n8.x4.shared.b16 {%0,%1,%2,%3}, [%4];"\
        : "=r"((R)[0]), "=r"((R)[1]), "=r"((R)[2]), "=r"((R)[3]) : "r"(addr))

#define MMA16816(ACC, A, B)                                                     \
    asm volatile("mma.sync.aligned.m16n8k16.row.col.f32.f16.f16.f32 "           \
        "{%0,%1,%2,%3}, {%4,%5,%6,%7}, {%8,%9}, {%0,%1,%2,%3};"                 \
        : "+f"((ACC)[0]), "+f"((ACC)[1]), "+f"((ACC)[2]), "+f"((ACC)[3])        \
        : "r"((A)[0]), "r"((A)[1]), "r"((A)[2]), "r"((A)[3]),                   \
          "r"((B)[0]), "r"((B)[1]))

// ---------------- Phase 1: transpose + fp16 convert (wide, batched) ----------------
// src: [z][R][C] fp32 -> dst: [z][C][R] fp16.  64x64 tile, 256 threads.
// Load: 1024 float4 (4/thread), coalesced 128B lines.
// Store: 512 uint4 (2/thread); each 8-lane group writes one full 128B dst row.
__global__ __launch_bounds__(256)
void tsplit_kernel(const float* __restrict__ src,
                   __half* __restrict__ dst,
                   int R, int C)
{
    __shared__ float tile[64][65];
    int b = blockIdx.z;
    src += (size_t)b * R * C;
    dst += (size_t)b * R * C;
    int p0 = blockIdx.x * 64;
    int c0 = blockIdx.y * 64;
    int tid = threadIdx.x;

    #pragma unroll
    for (int i = 0; i < 4; i++) {            // 1024 float4 chunks
        int q = tid + i * 256;
        int r = q >> 4;                      // c-row 0..63
        int c4 = q & 15;                     // float4 col 0..15
        float4 v = *(const float4*)(src + (size_t)(c0 + r) * C + p0 + c4 * 4);
        tile[r][c4 * 4 + 0] = v.x;
        tile[r][c4 * 4 + 1] = v.y;
        tile[r][c4 * 4 + 2] = v.z;
        tile[r][c4 * 4 + 3] = v.w;
    }
    __syncthreads();

    #pragma unroll
    for (int i = 0; i < 2; i++) {            // 512 uint4 chunks
        int q = tid + i * 256;
        int pr = q >> 3;                     // p-row 0..63
        int c8 = q & 7;                      // 8-channel group 0..7
        __half2 h[4];
        #pragma unroll
        for (int j = 0; j < 4; j++)
            h[j] = __floats2half2_rn(tile[c8 * 8 + j * 2][pr],
                                     tile[c8 * 8 + j * 2 + 1][pr]);
        uint4 st;
        st.x = *(uint32_t*)&h[0];
        st.y = *(uint32_t*)&h[1];
        st.z = *(uint32_t*)&h[2];
        st.w = *(uint32_t*)&h[3];
        *(uint4*)(dst + (size_t)(p0 + pr) * R + c0 + c8 * 8) = st;
    }
}

// ---------------- Phase 2: mma.sync fp16 GEMM (R8-best mainloop) ----------------
// SMEM stage: A = 128 rows x 128B, B = 128 rows x 128B.
// Row r, 16B chunk c stored at ((c ^ (r&7))<<4): conflict-free for cp.async
// stores and all ldmatrix phases.

__global__ __launch_bounds__(256, 2)
void gemm_mma_kernel(const float* __restrict__ bias, float* __restrict__ out)
{
    extern __shared__ char smem[];
    const uint32_t sbase = smem_u32(smem);

    const int tid  = threadIdx.x;
    const int lane = tid & 31;
    const int warp = tid >> 5;
    const int g    = lane >> 2;       // mma row within fragment
    const int tg   = lane & 3;        // mma col-pair selector
    const int wm   = warp & 3;        // 4 warps along M (32 rows each)
    const int wn   = warp >> 2;       // 2 warps along N (64 cols each)

    const int nb = blockIdx.x;        // 0..7   (N tile of 128)
    const int mb = blockIdx.y;        // 0..255 (M tile of 128)

    const __half* gA = g_xF + (size_t)mb * BM * K_TOTAL;
    const __half* gB = g_wF + (size_t)nb * BN * K_TOTAL;

    // ldmatrix per-lane addressing
    const int x7   = lane & 7;
    const int rA   = x7 + ((lane >> 3) & 1) * 8;          // row-in-16, A x4
    const int selA = lane >> 4;                           // k8 select, A x4
    const int rB   = ((lane >> 4) << 3) + x7;             // row-in-16, B x4 (nt pair)
    const int selB = (lane >> 3) & 1;                     // k8 select, B x4
    const uint32_t aBase = (uint32_t)(wm * 32 + rA) * ROWB;
    const uint32_t bBase = (uint32_t)(wn * 64 + rB) * ROWB;

    float acc[2][8][4];
    #pragma unroll
    for (int i = 0; i < 2; i++)
        #pragma unroll
        for (int j = 0; j < 8; j++)
            #pragma unroll
            for (int r = 0; r < 4; r++) acc[i][j][r] = 0.f;

    // ---- async staging of one k-stage (BK=64) into stage buffer ----
    auto stage_load = [&](int it, int buf) {
        const int k0 = it * BK;
        const uint32_t sA = sbase + buf * STAGE_BYTES;
        const uint32_t sB = sA + 128 * ROWB;
        #pragma unroll
        for (int i = 0; i < 4; i++) {                 // A: 1024 x 16B chunks
            int q = tid + i * 256;
            int r = q >> 3, c = q & 7;
            CP_ASYNC16(sA + (uint32_t)r * ROWB + (uint32_t)((c ^ (r & 7)) << 4),
                       gA + (size_t)r * K_TOTAL + k0 + c * 8);
        }
        #pragma unroll
        for (int i = 0; i < 4; i++) {                 // B: 1024 x 16B chunks
            int q = tid + i * 256;
            int r = q >> 3, c = q & 7;
            CP_ASYNC16(sB + (uint32_t)r * ROWB + (uint32_t)((c ^ (r & 7)) << 4),
                       gB + (size_t)r * K_TOTAL + k0 + c * 8);
        }
    };

    // prologue: two stages in flight
    stage_load(0, 0);
    CP_COMMIT();
    stage_load(1, 1);
    CP_COMMIT();

    for (int it = 0; it < KITERS; it++) {
        if (it + 1 < KITERS) { CP_WAIT1(); } else { CP_WAIT0(); }
        __syncthreads();          // releases compute(it) + certifies (it+2)%3 buffer
        if (it + 2 < KITERS) {
            stage_load(it + 2, (it + 2) % NSTAGE);
            CP_COMMIT();
        }

        const uint32_t sA = sbase + (it % NSTAGE) * STAGE_BYTES;
        const uint32_t sB = sA + 128 * ROWB;

        #pragma unroll
        for (int kc = 0; kc < 4; kc++) {              // four k16 chunks in BK=64
            uint32_t a[8], b[16];
            #pragma unroll
            for (int mt = 0; mt < 2; mt++)
                LDMX4(a + mt * 4, sA + aBase + (uint32_t)mt * 16 * ROWB
                                  + (uint32_t)(((kc * 2 + selA) ^ x7) << 4));
            #pragma unroll
            for (int ntp = 0; ntp < 4; ntp++)         // each LDMX4 covers 2 nt
                LDMX4(b + ntp * 4, sB + bBase + (uint32_t)ntp * 16 * ROWB
                                   + (uint32_t)(((kc * 2 + selB) ^ x7) << 4));
            #pragma unroll
            for (int mt = 0; mt < 2; mt++)
                #pragma unroll
                for (int nt = 0; nt < 8; nt++)
                    MMA16816(acc[mt][nt], a + mt * 4, b + nt * 2);
        }
    }

    // ---- epilogue: scatter to out[b][o][2h+i][2w+j], fused bias, streaming ----
    #pragma unroll
    for (int mt = 0; mt < 2; mt++) {
        int r0 = mb * 128 + wm * 32 + mt * 16 + g;
        #pragma unroll
        for (int half = 0; half < 2; half++) {
            int p  = r0 + half * 8;
            int bb = p >> 12;
            int h  = (p >> 6) & 63;
            int wp = p & 63;
            #pragma unroll
            for (int nt = 0; nt < 8; nt++) {
                int n  = nb * 128 + wn * 64 + nt * 8 + tg * 2;   // even -> (j=0, j=1)
                int o  = n >> 2;
                int ii = (n >> 1) & 1;
                float bo = __ldg(bias + o);
                size_t addr = (((size_t)(bb * 256 + o) * 128) + (h * 2 + ii)) * 128 + wp * 2;
                float2 v;
                v.x = acc[mt][nt][half * 2 + 0] + bo;
                v.y = acc[mt][nt][half * 2 + 1] + bo;
                __stcs((float2*)(out + addr), v);
            }
        }
    }
}

// ---------------- launch ----------------
extern "C" void kernel_launch(void* const* d_in, const int* in_sizes, int n_in,
                              void* d_out, int out_size)
{
    const float* x    = (const float*)d_in[0];   // [8,512,64,64]
    const float* wgt  = (const float*)d_in[1];   // [512,256,2,2] -> [512][1024]
    const float* bias = (const float*)d_in[2];   // [256]
    float* out = (float*)d_out;                  // [8,256,128,128]

    void *pxF, *pwF;
    cudaGetSymbolAddress(&pxF, g_xF);
    cudaGetSymbolAddress(&pwF, g_wF);
    __half* xF = (__half*)pxF;
    __half* wF = (__half*)pwF;

    // Phase 1: x transpose in ONE launch (z = batch); then tiny w transpose.
    tsplit_kernel<<<dim3(4096 / 64, 512 / 64, 8), 256>>>(x, xF, 512, 4096);
    tsplit_kernel<<<dim3(1024 / 64, 512 / 64, 1), 256>>>(wgt, wF, 512, 1024);

    // Phase 2
    static int attr_set = 0;
    if (!attr_set) {
        cudaFuncSetAttribute(gemm_mma_kernel,
                             cudaFuncAttributeMaxDynamicSharedMemorySize, SMEM_TOTAL);
        attr_set = 1;
    }
    dim3 grid(N_TOTAL / BN, M_TOTAL / BM);   // (8, 256) — nb fastest for A-tile L2 reuse
    gemm_mma_kernel<<<grid, 256, SMEM_TOTAL>>>(bias, out);
}